// round 7
// baseline (speedup 1.0000x reference)
#include <cuda_runtime.h>
#include <cuda_bf16.h>
#include <math.h>
#include <stdint.h>

#define BDIM 16
#define SDIM 4096
#define EDIM 512
#define HDIM 8
#define DH   64
#define TOK  (BDIM * SDIM)   // 65536 tokens
#define KDIM 512

// ---------------------------------------------------------------------------
// Scratch (allocation-free rule: device globals)
// ---------------------------------------------------------------------------
__device__ float          g_qkv[(size_t)TOK * 3 * EDIM];
__device__ __nv_bfloat16  g_xhi[(size_t)TOK * EDIM];
__device__ __nv_bfloat16  g_xlo[(size_t)TOK * EDIM];
__device__ __nv_bfloat16  g_ohi[(size_t)TOK * EDIM];
__device__ __nv_bfloat16  g_olo[(size_t)TOK * EDIM];
__device__ __nv_bfloat16  g_winhi[(size_t)3 * EDIM * EDIM];
__device__ __nv_bfloat16  g_winlo[(size_t)3 * EDIM * EDIM];
__device__ __nv_bfloat16  g_wouthi[(size_t)EDIM * EDIM];
__device__ __nv_bfloat16  g_woutlo[(size_t)EDIM * EDIM];

// ---------------------------------------------------------------------------
// PTX helpers (base PTX only — no sm_103a-gated features)
// ---------------------------------------------------------------------------
__device__ __forceinline__ uint32_t smem_u32(const void* p) {
    uint32_t a;
    asm("{ .reg .u64 t; cvta.to.shared.u64 t, %1; cvt.u32.u64 %0, t; }" : "=r"(a) : "l"(p));
    return a;
}
__device__ __forceinline__ void cpa16(uint32_t dst, const void* src) {
    asm volatile("cp.async.cg.shared.global [%0], [%1], 16;" :: "r"(dst), "l"(src));
}
#define CP_COMMIT() asm volatile("cp.async.commit_group;" ::: "memory")
#define CP_WAIT(n)  asm volatile("cp.async.wait_group %0;" :: "n"(n) : "memory")

__device__ __forceinline__ void ldsm4(uint32_t& r0, uint32_t& r1, uint32_t& r2, uint32_t& r3,
                                      uint32_t addr) {
    asm volatile("ldmatrix.sync.aligned.m8n8.x4.shared.b16 {%0,%1,%2,%3}, [%4];"
                 : "=r"(r0), "=r"(r1), "=r"(r2), "=r"(r3) : "r"(addr));
}
__device__ __forceinline__ void mma16816(float& d0, float& d1, float& d2, float& d3,
                                         uint32_t a0, uint32_t a1, uint32_t a2, uint32_t a3,
                                         uint32_t b0, uint32_t b1) {
    asm volatile(
        "mma.sync.aligned.m16n8k16.row.col.f32.bf16.bf16.f32 "
        "{%0,%1,%2,%3}, {%4,%5,%6,%7}, {%8,%9}, {%0,%1,%2,%3};"
        : "+f"(d0), "+f"(d1), "+f"(d2), "+f"(d3)
        : "r"(a0), "r"(a1), "r"(a2), "r"(a3), "r"(b0), "r"(b1));
}

// Swizzled smem offset within a K-major 32-col bf16 tile (row=64B, 4x16B chunks)
__device__ __forceinline__ uint32_t swz(int row, int ch) {
    return (uint32_t)(row * 64 + ((ch ^ ((row >> 1) & 3)) << 4));
}

// ---------------------------------------------------------------------------
// Elementwise fp32 -> (bf16 hi, bf16 lo) split
// ---------------------------------------------------------------------------
__global__ void __launch_bounds__(256) split_hilo(
    const float4* __restrict__ x, uint2* __restrict__ hi, uint2* __restrict__ lo, int n4)
{
    int i = blockIdx.x * 256 + threadIdx.x;
    if (i >= n4) return;
    float4 v = x[i];
    __nv_bfloat16 h0 = __float2bfloat16(v.x);
    __nv_bfloat16 h1 = __float2bfloat16(v.y);
    __nv_bfloat16 h2 = __float2bfloat16(v.z);
    __nv_bfloat16 h3 = __float2bfloat16(v.w);
    __nv_bfloat16 l0 = __float2bfloat16(v.x - __bfloat162float(h0));
    __nv_bfloat16 l1 = __float2bfloat16(v.y - __bfloat162float(h1));
    __nv_bfloat16 l2 = __float2bfloat16(v.z - __bfloat162float(h2));
    __nv_bfloat16 l3 = __float2bfloat16(v.w - __bfloat162float(h3));
    __nv_bfloat162 hA = {h0, h1}, hB = {h2, h3}, lA = {l0, l1}, lB = {l2, l3};
    uint2 H, L;
    H.x = *(uint32_t*)&hA; H.y = *(uint32_t*)&hB;
    L.x = *(uint32_t*)&lA; L.y = *(uint32_t*)&lB;
    hi[i] = H;
    lo[i] = L;
}

// ---------------------------------------------------------------------------
// HMMA GEMM: C = Ahi*Bhi^T + Ahi*Blo^T + Alo*Bhi^T + bias
// CTA tile 128x256, warp tile 64x64 (8 warps = 2x4), BK=32, 16 iterations,
// 3 rotating 48KB stages. Per k16: 12 ldsm (Ahi,Alo,Bhi) -> 64 MMAs ->
// 4 ldsm (Blo over Alo regs) -> 32 MMAs. 85 B smem per MMA (was 128).
// ---------------------------------------------------------------------------
#define STAGES 3
#define A8K   8192
#define B16K  16384
#define STAGE_BYTES (2 * A8K + 2 * B16K)   // Ahi | Alo | Bhi | Blo = 48KB
#define GEMM_SMEM (STAGES * STAGE_BYTES)
#define NCHUNK 16
#define BN_T 256

__global__ void __launch_bounds__(256, 1) gemm_hmma(
    const __nv_bfloat16* __restrict__ Ahi, const __nv_bfloat16* __restrict__ Alo,
    const __nv_bfloat16* __restrict__ Bhi, const __nv_bfloat16* __restrict__ Blo,
    const float* __restrict__ bias, float* __restrict__ C, int N)
{
    extern __shared__ char smem[];
    const uint32_t sb = smem_u32(smem);
    const int tid = threadIdx.x;
    const int wid = tid >> 5;
    const int lid = tid & 31;
    const int bm = blockIdx.y * 128;
    const int bn = blockIdx.x * BN_T;

    const int warp_m = (wid >> 2) * 64;   // 0 or 64
    const int warp_n = (wid & 3) * 64;    // 0,64,128,192

    // ---- hoisted load addressing
    const int lrow0 = tid >> 2;           // 0..63
    const int lch   = tid & 3;
    uint32_t dOff[4];
#pragma unroll
    for (int i = 0; i < 4; i++) dOff[i] = swz(lrow0 + 64 * i, lch);
    const size_t rowd = (size_t)lrow0 * KDIM + lch * 8;

    const __nv_bfloat16* pA[2] = { Ahi + (size_t)bm * KDIM + rowd,
                                   Alo + (size_t)bm * KDIM + rowd };
    const __nv_bfloat16* pB[2] = { Bhi + (size_t)bn * KDIM + rowd,
                                   Blo + (size_t)bn * KDIM + rowd };

    float acc[4][8][4];
#pragma unroll
    for (int i = 0; i < 4; i++)
#pragma unroll
        for (int j = 0; j < 8; j++)
#pragma unroll
            for (int r = 0; r < 4; r++) acc[i][j][r] = 0.0f;

    // Precomputed ldsm offsets (ks=0; ks=1 differs by ^32)
    uint32_t offA[4], offB[4];
#pragma unroll
    for (int fm = 0; fm < 4; fm++)
        offA[fm] = swz(warp_m + fm * 16 + (lid & 15), lid >> 4);
#pragma unroll
    for (int fb = 0; fb < 4; fb++)
        offB[fb] = swz(warp_n + fb * 16 + (lid & 15), lid >> 4);

    auto load_stage = [&](uint32_t sbase) {
#pragma unroll
        for (int t = 0; t < 2; t++) {                      // Ahi, Alo (128 rows)
            const uint32_t tb = sbase + t * A8K;
            cpa16(tb + dOff[0], pA[t]);
            cpa16(tb + dOff[1], pA[t] + (size_t)64 * KDIM);
            pA[t] += 32;
        }
#pragma unroll
        for (int t = 0; t < 2; t++) {                      // Bhi, Blo (256 rows)
            const uint32_t tb = sbase + 2 * A8K + t * B16K;
            cpa16(tb + dOff[0], pB[t]);
            cpa16(tb + dOff[1], pB[t] + (size_t)64 * KDIM);
            cpa16(tb + dOff[2], pB[t] + (size_t)128 * KDIM);
            cpa16(tb + dOff[3], pB[t] + (size_t)192 * KDIM);
            pB[t] += 32;
        }
        CP_COMMIT();
    };

    uint32_t sCur = sb, sNxt = sb + STAGE_BYTES, sPrv = sb + 2 * STAGE_BYTES;

    load_stage(sCur);
    load_stage(sNxt);

    for (int it = 0; it < NCHUNK; it++) {
        if (it < NCHUNK - 1) { CP_WAIT(1); } else { CP_WAIT(0); }
        __syncthreads();

        if (it + 2 < NCHUNK) load_stage(sPrv);

#pragma unroll
        for (int ks = 0; ks < 2; ks++) {
            const uint32_t kx = ks << 5;
            uint32_t a[4][4], al[4][4], bh[4][4];
            // 12 ldsm upfront: Ahi, Alo, Bhi
#pragma unroll
            for (int fm = 0; fm < 4; fm++)
                ldsm4(a[fm][0], a[fm][1], a[fm][2], a[fm][3],
                      sCur + (offA[fm] ^ kx));
#pragma unroll
            for (int fm = 0; fm < 4; fm++)
                ldsm4(al[fm][0], al[fm][1], al[fm][2], al[fm][3],
                      sCur + A8K + (offA[fm] ^ kx));
#pragma unroll
            for (int fb = 0; fb < 4; fb++)
                ldsm4(bh[fb][0], bh[fb][1], bh[fb][2], bh[fb][3],
                      sCur + 2 * A8K + (offB[fb] ^ kx));

            // 64 MMAs: Ahi*Bhi then Alo*Bhi
#pragma unroll
            for (int fm = 0; fm < 4; fm++)
#pragma unroll
                for (int fn = 0; fn < 8; fn++) {
                    const int fb = fn >> 1, hh = fn & 1;
                    mma16816(acc[fm][fn][0], acc[fm][fn][1], acc[fm][fn][2], acc[fm][fn][3],
                             a[fm][0], a[fm][1], a[fm][2], a[fm][3],
                             bh[fb][hh], bh[fb][hh + 2]);
                }
#pragma unroll
            for (int fm = 0; fm < 4; fm++)
#pragma unroll
                for (int fn = 0; fn < 8; fn++) {
                    const int fb = fn >> 1, hh = fn & 1;
                    mma16816(acc[fm][fn][0], acc[fm][fn][1], acc[fm][fn][2], acc[fm][fn][3],
                             al[fm][0], al[fm][1], al[fm][2], al[fm][3],
                             bh[fb][hh], bh[fb][hh + 2]);
                }

            // Blo reuses Alo regs (WAR only)
#pragma unroll
            for (int fb = 0; fb < 4; fb++)
                ldsm4(al[fb][0], al[fb][1], al[fb][2], al[fb][3],
                      sCur + 2 * A8K + B16K + (offB[fb] ^ kx));

            // 32 MMAs: Ahi*Blo
#pragma unroll
            for (int fm = 0; fm < 4; fm++)
#pragma unroll
                for (int fn = 0; fn < 8; fn++) {
                    const int fb = fn >> 1, hh = fn & 1;
                    mma16816(acc[fm][fn][0], acc[fm][fn][1], acc[fm][fn][2], acc[fm][fn][3],
                             a[fm][0], a[fm][1], a[fm][2], a[fm][3],
                             al[fb][hh], al[fb][hh + 2]);
                }
        }

        const uint32_t t = sPrv;
        sPrv = sCur; sCur = sNxt; sNxt = t;
    }

    // ---- Epilogue: direct fp32 stores + bias
    const int lr = lid >> 2;
    const int lc = (lid & 3) * 2;
#pragma unroll
    for (int fm = 0; fm < 4; fm++) {
#pragma unroll
        for (int fn = 0; fn < 8; fn++) {
            const int col = bn + warp_n + fn * 8 + lc;
            const float b0 = bias[col], b1 = bias[col + 1];
            const int row0 = bm + warp_m + fm * 16 + lr;
            float2 v0 = { acc[fm][fn][0] + b0, acc[fm][fn][1] + b1 };
            float2 v1 = { acc[fm][fn][2] + b0, acc[fm][fn][3] + b1 };
            *(float2*)(C + (size_t)row0 * N + col)       = v0;
            *(float2*)(C + (size_t)(row0 + 8) * N + col) = v1;
        }
    }
}

// ---------------------------------------------------------------------------
// Attention over the batch axis (16) at each (s, h); emits o split hi/lo bf16.
// ---------------------------------------------------------------------------
__global__ void __launch_bounds__(128) attn_kernel(
    const float* __restrict__ qkv,
    __nv_bfloat16* __restrict__ ohi, __nv_bfloat16* __restrict__ olo)
{
    const int s = blockIdx.x;
    const int h = blockIdx.y;

    __shared__ float q[BDIM][66];
    __shared__ float k[BDIM][66];
    __shared__ float v[BDIM][66];
    __shared__ float sc[BDIM][BDIM + 1];

    const int tid = threadIdx.x;

    for (int j = tid; j < BDIM * DH; j += 128) {
        const int b = j >> 6;
        const int d = j & 63;
        const size_t base = ((size_t)(b * SDIM + s)) * (3 * EDIM) + h * DH + d;
        q[b][d] = qkv[base];
        k[b][d] = qkv[base + EDIM];
        v[b][d] = qkv[base + 2 * EDIM];
    }
    __syncthreads();

    const float scale = 0.125f;
#pragma unroll
    for (int e = tid; e < BDIM * BDIM; e += 128) {
        const int bq = e >> 4;
        const int bk = e & 15;
        float acc = 0.0f;
#pragma unroll
        for (int d = 0; d < DH; d++)
            acc = fmaf(q[bq][d], k[bk][d], acc);
        sc[bq][bk] = acc * scale;
    }
    __syncthreads();

    if (tid < BDIM) {
        float m = -1e30f;
#pragma unroll
        for (int j = 0; j < BDIM; j++) m = fmaxf(m, sc[tid][j]);
        float sum = 0.0f;
        float e_[BDIM];
#pragma unroll
        for (int j = 0; j < BDIM; j++) { e_[j] = expf(sc[tid][j] - m); sum += e_[j]; }
        const float inv = 1.0f / sum;
#pragma unroll
        for (int j = 0; j < BDIM; j++) sc[tid][j] = e_[j] * inv;
    }
    __syncthreads();

    const int bq = tid >> 3;
    const int dl = tid & 7;
    const size_t obase = ((size_t)(bq * SDIM + s)) * EDIM + h * DH;
#pragma unroll
    for (int i = 0; i < 8; i++) {
        const int d = dl + i * 8;
        float acc = 0.0f;
#pragma unroll
        for (int bk = 0; bk < BDIM; bk++)
            acc = fmaf(sc[bq][bk], v[bk][d], acc);
        __nv_bfloat16 hi = __float2bfloat16(acc);
        ohi[obase + d] = hi;
        olo[obase + d] = __float2bfloat16(acc - __bfloat162float(hi));
    }
}

// ---------------------------------------------------------------------------
extern "C" void kernel_launch(void* const* d_in, const int* in_sizes, int n_in,
                              void* d_out, int out_size)
{
    const float* x     = (const float*)d_in[0];
    const float* W_in  = (const float*)d_in[1];
    const float* b_in  = (const float*)d_in[2];
    const float* W_out = (const float*)d_in[3];
    const float* b_out = (const float*)d_in[4];
    float* out = (float*)d_out;

    float *qkv;
    __nv_bfloat16 *xhi, *xlo, *ohi, *olo, *winhi, *winlo, *wouthi, *woutlo;
    cudaGetSymbolAddress((void**)&qkv, g_qkv);
    cudaGetSymbolAddress((void**)&xhi, g_xhi);
    cudaGetSymbolAddress((void**)&xlo, g_xlo);
    cudaGetSymbolAddress((void**)&ohi, g_ohi);
    cudaGetSymbolAddress((void**)&olo, g_olo);
    cudaGetSymbolAddress((void**)&winhi, g_winhi);
    cudaGetSymbolAddress((void**)&winlo, g_winlo);
    cudaGetSymbolAddress((void**)&wouthi, g_wouthi);
    cudaGetSymbolAddress((void**)&woutlo, g_woutlo);

    cudaFuncSetAttribute(gemm_hmma, cudaFuncAttributeMaxDynamicSharedMemorySize, GEMM_SMEM);

    // fp32 -> bf16 hi/lo splits
    {
        int n4 = TOK * EDIM / 4;
        split_hilo<<<(n4 + 255) / 256, 256>>>((const float4*)x, (uint2*)xhi, (uint2*)xlo, n4);
        n4 = 3 * EDIM * EDIM / 4;
        split_hilo<<<(n4 + 255) / 256, 256>>>((const float4*)W_in, (uint2*)winhi, (uint2*)winlo, n4);
        n4 = EDIM * EDIM / 4;
        split_hilo<<<(n4 + 255) / 256, 256>>>((const float4*)W_out, (uint2*)wouthi, (uint2*)woutlo, n4);
    }

    // 1) QKV projection -> fp32 qkv   (N = 1536 -> 6 N-tiles)
    dim3 g1(3 * EDIM / BN_T, TOK / 128);
    gemm_hmma<<<g1, 256, GEMM_SMEM>>>(xhi, xlo, winhi, winlo, b_in, qkv, 3 * EDIM);

    // 2) Batch-axis attention; emits o split hi/lo bf16
    dim3 g2(SDIM, HDIM);
    attn_kernel<<<g2, 128>>>(qkv, ohi, olo);

    // 3) Output projection   (N = 512 -> 2 N-tiles)
    dim3 g3(EDIM / BN_T, TOK / 128);
    gemm_hmma<<<g3, 256, GEMM_SMEM>>>(ohi, olo, wouthi, woutlo, b_out, out, EDIM);
}

// round 8
// speedup vs baseline: 2.1492x; 2.1492x over previous
#include <cuda_runtime.h>
#include <cuda_fp16.h>
#include <math.h>
#include <stdint.h>

#define BDIM 16
#define SDIM 4096
#define EDIM 512
#define HDIM 8
#define DH   64
#define TOK  (BDIM * SDIM)   // 65536 tokens
#define KDIM 512

// ---------------------------------------------------------------------------
// Scratch (allocation-free rule: device globals)
// ---------------------------------------------------------------------------
__device__ float   g_qkv[(size_t)TOK * 3 * EDIM];
__device__ __half  g_xh [(size_t)TOK * EDIM];
__device__ __half  g_oh [(size_t)TOK * EDIM];
__device__ __half  g_winh [(size_t)3 * EDIM * EDIM];
__device__ __half  g_wouth[(size_t)EDIM * EDIM];

// ---------------------------------------------------------------------------
// PTX helpers (base PTX only)
// ---------------------------------------------------------------------------
__device__ __forceinline__ uint32_t smem_u32(const void* p) {
    uint32_t a;
    asm("{ .reg .u64 t; cvta.to.shared.u64 t, %1; cvt.u32.u64 %0, t; }" : "=r"(a) : "l"(p));
    return a;
}
__device__ __forceinline__ void cpa16(uint32_t dst, const void* src) {
    asm volatile("cp.async.cg.shared.global [%0], [%1], 16;" :: "r"(dst), "l"(src));
}
#define CP_COMMIT() asm volatile("cp.async.commit_group;" ::: "memory")
#define CP_WAIT(n)  asm volatile("cp.async.wait_group %0;" :: "n"(n) : "memory")

__device__ __forceinline__ void ldsm4(uint32_t& r0, uint32_t& r1, uint32_t& r2, uint32_t& r3,
                                      uint32_t addr) {
    asm volatile("ldmatrix.sync.aligned.m8n8.x4.shared.b16 {%0,%1,%2,%3}, [%4];"
                 : "=r"(r0), "=r"(r1), "=r"(r2), "=r"(r3) : "r"(addr));
}
__device__ __forceinline__ void mma16816(float& d0, float& d1, float& d2, float& d3,
                                         uint32_t a0, uint32_t a1, uint32_t a2, uint32_t a3,
                                         uint32_t b0, uint32_t b1) {
    asm volatile(
        "mma.sync.aligned.m16n8k16.row.col.f32.f16.f16.f32 "
        "{%0,%1,%2,%3}, {%4,%5,%6,%7}, {%8,%9}, {%0,%1,%2,%3};"
        : "+f"(d0), "+f"(d1), "+f"(d2), "+f"(d3)
        : "r"(a0), "r"(a1), "r"(a2), "r"(a3), "r"(b0), "r"(b1));
}

// Swizzled offset in a 128-row x 64-col fp16 tile (row = 128 B = 8 x 16B chunks)
__device__ __forceinline__ uint32_t swz128(int row, int ch) {
    return (uint32_t)(row * 128 + ((ch ^ (row & 7)) << 4));
}

// ---------------------------------------------------------------------------
// fp32 -> fp16 convert (vectorized)
// ---------------------------------------------------------------------------
__global__ void __launch_bounds__(256) conv_f16(
    const float4* __restrict__ x, uint2* __restrict__ h, int n4)
{
    int i = blockIdx.x * 256 + threadIdx.x;
    if (i >= n4) return;
    float4 v = x[i];
    __half2 a = __floats2half2_rn(v.x, v.y);
    __half2 b = __floats2half2_rn(v.z, v.w);
    uint2 o;
    o.x = *(uint32_t*)&a;
    o.y = *(uint32_t*)&b;
    h[i] = o;
}

// ---------------------------------------------------------------------------
// fp16 HMMA GEMM: C[M,N] = A[M,K] * B[N,K]^T + bias, fp32 accum.
// CTA tile 128x128, warp tile 64x32 (8 warps), BK=64, 8 iterations,
// 3 rotating 32KB stages (A 16KB | B 16KB), distance-2 cp.async prefetch.
// ---------------------------------------------------------------------------
#define STAGES 3
#define TILE16K 16384
#define STAGE_BYTES (2 * TILE16K)
#define GEMM_SMEM (STAGES * STAGE_BYTES)
#define NCHUNK 8                         // 512 / 64

__global__ void __launch_bounds__(256, 2) gemm_hmma(
    const __half* __restrict__ A, const __half* __restrict__ B,
    const float* __restrict__ bias, float* __restrict__ C, int N)
{
    extern __shared__ char smem[];
    const uint32_t sb = smem_u32(smem);
    const int tid = threadIdx.x;
    const int wid = tid >> 5;
    const int lid = tid & 31;
    const int bm = blockIdx.y * 128;
    const int bn = blockIdx.x * 128;

    const int warp_m = (wid >> 2) * 64;   // 0 or 64
    const int warp_n = (wid & 3) * 32;    // 0,32,64,96

    // ---- load addressing: thread covers (row = tid>>3 + 32i, chunk = tid&7)
    const int lrow = tid >> 3;            // 0..31
    const int lch  = tid & 7;
    uint32_t dOff[4];
#pragma unroll
    for (int i = 0; i < 4; i++) dOff[i] = swz128(lrow + 32 * i, lch);

    const __half* pA = A + (size_t)(bm + lrow) * KDIM + lch * 8;
    const __half* pB = B + (size_t)(bn + lrow) * KDIM + lch * 8;

    float acc[4][4][4];
#pragma unroll
    for (int i = 0; i < 4; i++)
#pragma unroll
        for (int j = 0; j < 4; j++)
#pragma unroll
            for (int r = 0; r < 4; r++) acc[i][j][r] = 0.0f;

    // ldsm offsets for kk=0; kk advances by XOR (kk<<5) (chunk bits 1-2)
    uint32_t offA[4], offB[2];
#pragma unroll
    for (int fm = 0; fm < 4; fm++)
        offA[fm] = swz128(warp_m + fm * 16 + (lid & 15), lid >> 4);
#pragma unroll
    for (int fb = 0; fb < 2; fb++)
        offB[fb] = swz128(warp_n + fb * 16 + (lid & 15), lid >> 4);

    auto load_stage = [&](uint32_t sbase) {
#pragma unroll
        for (int i = 0; i < 4; i++)
            cpa16(sbase + dOff[i], pA + (size_t)(32 * i) * KDIM);
#pragma unroll
        for (int i = 0; i < 4; i++)
            cpa16(sbase + TILE16K + dOff[i], pB + (size_t)(32 * i) * KDIM);
        pA += 64;
        pB += 64;
        CP_COMMIT();
    };

    uint32_t sCur = sb, sNxt = sb + STAGE_BYTES, sPrv = sb + 2 * STAGE_BYTES;

    load_stage(sCur);
    load_stage(sNxt);

    for (int it = 0; it < NCHUNK; it++) {
        if (it < NCHUNK - 1) { CP_WAIT(1); } else { CP_WAIT(0); }
        __syncthreads();

        if (it + 2 < NCHUNK) load_stage(sPrv);

#pragma unroll
        for (int kk = 0; kk < 4; kk++) {             // four k16 per BK=64
            const uint32_t kx = (uint32_t)kk << 5;   // XOR into chunk bits 1-2
            uint32_t a[4][4], b[2][4];
#pragma unroll
            for (int fm = 0; fm < 4; fm++)
                ldsm4(a[fm][0], a[fm][1], a[fm][2], a[fm][3],
                      sCur + (offA[fm] ^ kx));
#pragma unroll
            for (int fb = 0; fb < 2; fb++)
                ldsm4(b[fb][0], b[fb][1], b[fb][2], b[fb][3],
                      sCur + TILE16K + (offB[fb] ^ kx));

#pragma unroll
            for (int fm = 0; fm < 4; fm++)
#pragma unroll
                for (int fn = 0; fn < 4; fn++) {
                    const int fb = fn >> 1, hh = fn & 1;
                    mma16816(acc[fm][fn][0], acc[fm][fn][1], acc[fm][fn][2], acc[fm][fn][3],
                             a[fm][0], a[fm][1], a[fm][2], a[fm][3],
                             b[fb][hh], b[fb][hh + 2]);
                }
        }

        const uint32_t t = sPrv;
        sPrv = sCur; sCur = sNxt; sNxt = t;
    }

    // ---- Epilogue: direct fp32 stores + bias
    const int lr = lid >> 2;
    const int lc = (lid & 3) * 2;
#pragma unroll
    for (int fm = 0; fm < 4; fm++) {
#pragma unroll
        for (int fn = 0; fn < 4; fn++) {
            const int col = bn + warp_n + fn * 8 + lc;
            const float b0 = bias[col], b1 = bias[col + 1];
            const int row0 = bm + warp_m + fm * 16 + lr;
            float2 v0 = { acc[fm][fn][0] + b0, acc[fm][fn][1] + b1 };
            float2 v1 = { acc[fm][fn][2] + b0, acc[fm][fn][3] + b1 };
            *(float2*)(C + (size_t)row0 * N + col)       = v0;
            *(float2*)(C + (size_t)(row0 + 8) * N + col) = v1;
        }
    }
}

// ---------------------------------------------------------------------------
// Attention over the batch axis (16) at each (s, h); emits fp16 o.
// ---------------------------------------------------------------------------
__global__ void __launch_bounds__(128) attn_kernel(
    const float* __restrict__ qkv, __half* __restrict__ oh)
{
    const int s = blockIdx.x;
    const int h = blockIdx.y;

    __shared__ float q[BDIM][66];
    __shared__ float k[BDIM][66];
    __shared__ float v[BDIM][66];
    __shared__ float sc[BDIM][BDIM + 1];

    const int tid = threadIdx.x;

    for (int j = tid; j < BDIM * DH; j += 128) {
        const int b = j >> 6;
        const int d = j & 63;
        const size_t base = ((size_t)(b * SDIM + s)) * (3 * EDIM) + h * DH + d;
        q[b][d] = qkv[base];
        k[b][d] = qkv[base + EDIM];
        v[b][d] = qkv[base + 2 * EDIM];
    }
    __syncthreads();

    const float scale = 0.125f;
#pragma unroll
    for (int e = tid; e < BDIM * BDIM; e += 128) {
        const int bq = e >> 4;
        const int bk = e & 15;
        float acc = 0.0f;
#pragma unroll
        for (int d = 0; d < DH; d++)
            acc = fmaf(q[bq][d], k[bk][d], acc);
        sc[bq][bk] = acc * scale;
    }
    __syncthreads();

    if (tid < BDIM) {
        float m = -1e30f;
#pragma unroll
        for (int j = 0; j < BDIM; j++) m = fmaxf(m, sc[tid][j]);
        float sum = 0.0f;
        float e_[BDIM];
#pragma unroll
        for (int j = 0; j < BDIM; j++) { e_[j] = expf(sc[tid][j] - m); sum += e_[j]; }
        const float inv = 1.0f / sum;
#pragma unroll
        for (int j = 0; j < BDIM; j++) sc[tid][j] = e_[j] * inv;
    }
    __syncthreads();

    const int bq = tid >> 3;
    const int dl = tid & 7;
    const size_t obase = ((size_t)(bq * SDIM + s)) * EDIM + h * DH;
#pragma unroll
    for (int i = 0; i < 8; i++) {
        const int d = dl + i * 8;
        float acc = 0.0f;
#pragma unroll
        for (int bk = 0; bk < BDIM; bk++)
            acc = fmaf(sc[bq][bk], v[bk][d], acc);
        oh[obase + d] = __float2half_rn(acc);
    }
}

// ---------------------------------------------------------------------------
extern "C" void kernel_launch(void* const* d_in, const int* in_sizes, int n_in,
                              void* d_out, int out_size)
{
    const float* x     = (const float*)d_in[0];
    const float* W_in  = (const float*)d_in[1];
    const float* b_in  = (const float*)d_in[2];
    const float* W_out = (const float*)d_in[3];
    const float* b_out = (const float*)d_in[4];
    float* out = (float*)d_out;

    float* qkv;
    __half *xh, *oh, *winh, *wouth;
    cudaGetSymbolAddress((void**)&qkv, g_qkv);
    cudaGetSymbolAddress((void**)&xh, g_xh);
    cudaGetSymbolAddress((void**)&oh, g_oh);
    cudaGetSymbolAddress((void**)&winh, g_winh);
    cudaGetSymbolAddress((void**)&wouth, g_wouth);

    cudaFuncSetAttribute(gemm_hmma, cudaFuncAttributeMaxDynamicSharedMemorySize, GEMM_SMEM);

    // fp32 -> fp16 conversions
    {
        int n4 = TOK * EDIM / 4;
        conv_f16<<<(n4 + 255) / 256, 256>>>((const float4*)x, (uint2*)xh, n4);
        n4 = 3 * EDIM * EDIM / 4;
        conv_f16<<<(n4 + 255) / 256, 256>>>((const float4*)W_in, (uint2*)winh, n4);
        n4 = EDIM * EDIM / 4;
        conv_f16<<<(n4 + 255) / 256, 256>>>((const float4*)W_out, (uint2*)wouth, n4);
    }

    // 1) QKV projection -> fp32 qkv
    dim3 g1(3 * EDIM / 128, TOK / 128);
    gemm_hmma<<<g1, 256, GEMM_SMEM>>>(xh, winh, b_in, qkv, 3 * EDIM);

    // 2) Batch-axis attention; emits fp16 o
    dim3 g2(SDIM, HDIM);
    attn_kernel<<<g2, 128>>>(qkv, oh);

    // 3) Output projection
    dim3 g3(EDIM / 128, TOK / 128);
    gemm_hmma<<<g3, 256, GEMM_SMEM>>>(oh, wouth, b_out, out, EDIM);
}

// round 9
// speedup vs baseline: 2.3952x; 1.1145x over previous
#include <cuda_runtime.h>
#include <cuda_fp16.h>
#include <math.h>
#include <stdint.h>

#define BDIM 16
#define SDIM 4096
#define EDIM 512
#define HDIM 8
#define DH   64
#define TOK  (BDIM * SDIM)   // 65536 tokens
#define KDIM 512

// ---------------------------------------------------------------------------
// Scratch (allocation-free rule: device globals)
// ---------------------------------------------------------------------------
__device__ float   g_qkv[(size_t)TOK * 3 * EDIM];
__device__ __half  g_xh [(size_t)TOK * EDIM];
__device__ __half  g_oh [(size_t)TOK * EDIM];
__device__ __half  g_winh [(size_t)3 * EDIM * EDIM];
__device__ __half  g_wouth[(size_t)EDIM * EDIM];

// ---------------------------------------------------------------------------
// PTX helpers (base PTX only)
// ---------------------------------------------------------------------------
__device__ __forceinline__ uint32_t smem_u32(const void* p) {
    uint32_t a;
    asm("{ .reg .u64 t; cvta.to.shared.u64 t, %1; cvt.u32.u64 %0, t; }" : "=r"(a) : "l"(p));
    return a;
}
__device__ __forceinline__ void cpa16(uint32_t dst, const void* src) {
    asm volatile("cp.async.cg.shared.global [%0], [%1], 16;" :: "r"(dst), "l"(src));
}
#define CP_COMMIT() asm volatile("cp.async.commit_group;" ::: "memory")
#define CP_WAIT(n)  asm volatile("cp.async.wait_group %0;" :: "n"(n) : "memory")

__device__ __forceinline__ void ldsm4(uint32_t& r0, uint32_t& r1, uint32_t& r2, uint32_t& r3,
                                      uint32_t addr) {
    asm volatile("ldmatrix.sync.aligned.m8n8.x4.shared.b16 {%0,%1,%2,%3}, [%4];"
                 : "=r"(r0), "=r"(r1), "=r"(r2), "=r"(r3) : "r"(addr));
}
__device__ __forceinline__ void mma16816(float& d0, float& d1, float& d2, float& d3,
                                         uint32_t a0, uint32_t a1, uint32_t a2, uint32_t a3,
                                         uint32_t b0, uint32_t b1) {
    asm volatile(
        "mma.sync.aligned.m16n8k16.row.col.f32.f16.f16.f32 "
        "{%0,%1,%2,%3}, {%4,%5,%6,%7}, {%8,%9}, {%0,%1,%2,%3};"
        : "+f"(d0), "+f"(d1), "+f"(d2), "+f"(d3)
        : "r"(a0), "r"(a1), "r"(a2), "r"(a3), "r"(b0), "r"(b1));
}

// Swizzled offset in a 128-row x 64-col fp16 tile (row = 128 B = 8 x 16B chunks)
__device__ __forceinline__ uint32_t swz128(int row, int ch) {
    return (uint32_t)(row * 128 + ((ch ^ (row & 7)) << 4));
}

// ---------------------------------------------------------------------------
// fp32 -> fp16 convert (vectorized)
// ---------------------------------------------------------------------------
__global__ void __launch_bounds__(256) conv_f16(
    const float4* __restrict__ x, uint2* __restrict__ h, int n4)
{
    int i = blockIdx.x * 256 + threadIdx.x;
    if (i >= n4) return;
    float4 v = x[i];
    __half2 a = __floats2half2_rn(v.x, v.y);
    __half2 b = __floats2half2_rn(v.z, v.w);
    uint2 o;
    o.x = *(uint32_t*)&a;
    o.y = *(uint32_t*)&b;
    h[i] = o;
}

// ---------------------------------------------------------------------------
// fp16 HMMA GEMM (unchanged from R8): 128x128 CTA, BK=64, 3 stages.
// ---------------------------------------------------------------------------
#define STAGES 3
#define TILE16K 16384
#define STAGE_BYTES (2 * TILE16K)
#define GEMM_SMEM (STAGES * STAGE_BYTES)
#define NCHUNK 8

__global__ void __launch_bounds__(256, 2) gemm_hmma(
    const __half* __restrict__ A, const __half* __restrict__ B,
    const float* __restrict__ bias, float* __restrict__ C, int N)
{
    extern __shared__ char smem[];
    const uint32_t sb = smem_u32(smem);
    const int tid = threadIdx.x;
    const int wid = tid >> 5;
    const int lid = tid & 31;
    const int bm = blockIdx.y * 128;
    const int bn = blockIdx.x * 128;

    const int warp_m = (wid >> 2) * 64;
    const int warp_n = (wid & 3) * 32;

    const int lrow = tid >> 3;
    const int lch  = tid & 7;
    uint32_t dOff[4];
#pragma unroll
    for (int i = 0; i < 4; i++) dOff[i] = swz128(lrow + 32 * i, lch);

    const __half* pA = A + (size_t)(bm + lrow) * KDIM + lch * 8;
    const __half* pB = B + (size_t)(bn + lrow) * KDIM + lch * 8;

    float acc[4][4][4];
#pragma unroll
    for (int i = 0; i < 4; i++)
#pragma unroll
        for (int j = 0; j < 4; j++)
#pragma unroll
            for (int r = 0; r < 4; r++) acc[i][j][r] = 0.0f;

    uint32_t offA[4], offB[2];
#pragma unroll
    for (int fm = 0; fm < 4; fm++)
        offA[fm] = swz128(warp_m + fm * 16 + (lid & 15), lid >> 4);
#pragma unroll
    for (int fb = 0; fb < 2; fb++)
        offB[fb] = swz128(warp_n + fb * 16 + (lid & 15), lid >> 4);

    auto load_stage = [&](uint32_t sbase) {
#pragma unroll
        for (int i = 0; i < 4; i++)
            cpa16(sbase + dOff[i], pA + (size_t)(32 * i) * KDIM);
#pragma unroll
        for (int i = 0; i < 4; i++)
            cpa16(sbase + TILE16K + dOff[i], pB + (size_t)(32 * i) * KDIM);
        pA += 64;
        pB += 64;
        CP_COMMIT();
    };

    uint32_t sCur = sb, sNxt = sb + STAGE_BYTES, sPrv = sb + 2 * STAGE_BYTES;

    load_stage(sCur);
    load_stage(sNxt);

    for (int it = 0; it < NCHUNK; it++) {
        if (it < NCHUNK - 1) { CP_WAIT(1); } else { CP_WAIT(0); }
        __syncthreads();

        if (it + 2 < NCHUNK) load_stage(sPrv);

#pragma unroll
        for (int kk = 0; kk < 4; kk++) {
            const uint32_t kx = (uint32_t)kk << 5;
            uint32_t a[4][4], b[2][4];
#pragma unroll
            for (int fm = 0; fm < 4; fm++)
                ldsm4(a[fm][0], a[fm][1], a[fm][2], a[fm][3],
                      sCur + (offA[fm] ^ kx));
#pragma unroll
            for (int fb = 0; fb < 2; fb++)
                ldsm4(b[fb][0], b[fb][1], b[fb][2], b[fb][3],
                      sCur + TILE16K + (offB[fb] ^ kx));

#pragma unroll
            for (int fm = 0; fm < 4; fm++)
#pragma unroll
                for (int fn = 0; fn < 4; fn++) {
                    const int fb = fn >> 1, hh = fn & 1;
                    mma16816(acc[fm][fn][0], acc[fm][fn][1], acc[fm][fn][2], acc[fm][fn][3],
                             a[fm][0], a[fm][1], a[fm][2], a[fm][3],
                             b[fb][hh], b[fb][hh + 2]);
                }
        }

        const uint32_t t = sPrv;
        sPrv = sCur; sCur = sNxt; sNxt = t;
    }

    const int lr = lid >> 2;
    const int lc = (lid & 3) * 2;
#pragma unroll
    for (int fm = 0; fm < 4; fm++) {
#pragma unroll
        for (int fn = 0; fn < 4; fn++) {
            const int col = bn + warp_n + fn * 8 + lc;
            const float b0 = bias[col], b1 = bias[col + 1];
            const int row0 = bm + warp_m + fm * 16 + lr;
            float2 v0 = { acc[fm][fn][0] + b0, acc[fm][fn][1] + b1 };
            float2 v1 = { acc[fm][fn][2] + b0, acc[fm][fn][3] + b1 };
            *(float2*)(C + (size_t)row0 * N + col)       = v0;
            *(float2*)(C + (size_t)(row0 + 8) * N + col) = v1;
        }
    }
}

// ---------------------------------------------------------------------------
// Attention: one CTA per sequence position s, 256 threads, warp = head.
// Single __syncthreads after the coalesced load; all per-head work is
// warp-private (scores/softmax/AV via __syncwarp).
// ---------------------------------------------------------------------------
#define SPAD 514                       // float stride: even (float2-aligned),
                                       // 514 mod 32 = 2 -> rows hit distinct banks
#define ATT_SMEM ((3 * BDIM * SPAD + HDIM * BDIM * 17) * 4)

__global__ void __launch_bounds__(256, 2) attn_kernel(
    const float* __restrict__ qkv, __half* __restrict__ oh)
{
    const int s = blockIdx.x;
    extern __shared__ float sm[];
    float* q  = sm;                    // [16][SPAD]
    float* k  = q + BDIM * SPAD;
    float* v  = k + BDIM * SPAD;
    float* sc = v + BDIM * SPAD;       // [8][16][17]

    const int tid = threadIdx.x;

    // ---- coalesced load: 16 rows x 1536 contiguous floats (384 float4 each)
#pragma unroll
    for (int i = 0; i < 24; i++) {
        const int idx = tid + 256 * i;         // 0..6143
        const int b   = idx / 384;
        const int c4  = idx - b * 384;
        const int col = c4 * 4;
        float4 d = *(const float4*)(qkv + ((size_t)(b * SDIM + s)) * 1536 + col);
        float* dst;
        if (col < 512)       dst = q + b * SPAD + col;
        else if (col < 1024) dst = k + b * SPAD + (col - 512);
        else                 dst = v + b * SPAD + (col - 1024);
        dst[0] = d.x; dst[1] = d.y; dst[2] = d.z; dst[3] = d.w;
    }
    __syncthreads();

    const int w   = tid >> 5;          // head
    const int lid = tid & 31;
    const int hd  = w * DH;
    float* scw = sc + w * (BDIM * 17);

    // ---- scores: lane computes 8 scores (bq = lid&15, bk = (lid>>4)*8 + j)
    {
        const int bq  = lid & 15;
        const int bk0 = (lid >> 4) * 8;
        float acc[8];
#pragma unroll
        for (int j = 0; j < 8; j++) acc[j] = 0.0f;
        const float* qrow = q + bq * SPAD + hd;
#pragma unroll 8
        for (int d2 = 0; d2 < 32; d2++) {
            const float2 qv = *(const float2*)(qrow + 2 * d2);
#pragma unroll
            for (int j = 0; j < 8; j++) {
                const float2 kv = *(const float2*)(k + (bk0 + j) * SPAD + hd + 2 * d2);
                acc[j] += qv.x * kv.x + qv.y * kv.y;
            }
        }
#pragma unroll
        for (int j = 0; j < 8; j++)
            scw[bq * 17 + bk0 + j] = acc[j] * 0.125f;
    }
    __syncwarp();

    // ---- softmax: lanes 0..15, one row each (over key axis)
    if (lid < 16) {
        float* row = scw + lid * 17;
        float m = -1e30f;
#pragma unroll
        for (int j = 0; j < 16; j++) m = fmaxf(m, row[j]);
        float sum = 0.0f;
        float e_[16];
#pragma unroll
        for (int j = 0; j < 16; j++) { e_[j] = expf(row[j] - m); sum += e_[j]; }
        const float inv = 1.0f / sum;
#pragma unroll
        for (int j = 0; j < 16; j++) row[j] = e_[j] * inv;
    }
    __syncwarp();

    // ---- AV: lane owns (bq = lid>>1, 32 d-columns), fp16 vectorized store
    {
        const int bq    = lid >> 1;
        const int dbase = (lid & 1) * 32;
        float o[32];
#pragma unroll
        for (int i = 0; i < 32; i++) o[i] = 0.0f;
#pragma unroll
        for (int bk = 0; bk < BDIM; bk++) {
            const float sv = scw[bq * 17 + bk];
            const float* vr = v + bk * SPAD + hd + dbase;
#pragma unroll
            for (int i2 = 0; i2 < 16; i2++) {
                const float2 vv = *(const float2*)(vr + 2 * i2);
                o[2 * i2]     += sv * vv.x;
                o[2 * i2 + 1] += sv * vv.y;
            }
        }
        uint32_t h2[16];
#pragma unroll
        for (int i2 = 0; i2 < 16; i2++) {
            __half2 hh = __floats2half2_rn(o[2 * i2], o[2 * i2 + 1]);
            h2[i2] = *(uint32_t*)&hh;
        }
        __half* dst = oh + ((size_t)(bq * SDIM + s)) * EDIM + hd + dbase;
#pragma unroll
        for (int c = 0; c < 4; c++) {
            uint4 pk = { h2[4 * c], h2[4 * c + 1], h2[4 * c + 2], h2[4 * c + 3] };
            *(uint4*)(dst + 8 * c) = pk;
        }
    }
}

// ---------------------------------------------------------------------------
extern "C" void kernel_launch(void* const* d_in, const int* in_sizes, int n_in,
                              void* d_out, int out_size)
{
    const float* x     = (const float*)d_in[0];
    const float* W_in  = (const float*)d_in[1];
    const float* b_in  = (const float*)d_in[2];
    const float* W_out = (const float*)d_in[3];
    const float* b_out = (const float*)d_in[4];
    float* out = (float*)d_out;

    float* qkv;
    __half *xh, *oh, *winh, *wouth;
    cudaGetSymbolAddress((void**)&qkv, g_qkv);
    cudaGetSymbolAddress((void**)&xh, g_xh);
    cudaGetSymbolAddress((void**)&oh, g_oh);
    cudaGetSymbolAddress((void**)&winh, g_winh);
    cudaGetSymbolAddress((void**)&wouth, g_wouth);

    cudaFuncSetAttribute(gemm_hmma, cudaFuncAttributeMaxDynamicSharedMemorySize, GEMM_SMEM);
    cudaFuncSetAttribute(attn_kernel, cudaFuncAttributeMaxDynamicSharedMemorySize, ATT_SMEM);

    // fp32 -> fp16 conversions
    {
        int n4 = TOK * EDIM / 4;
        conv_f16<<<(n4 + 255) / 256, 256>>>((const float4*)x, (uint2*)xh, n4);
        n4 = 3 * EDIM * EDIM / 4;
        conv_f16<<<(n4 + 255) / 256, 256>>>((const float4*)W_in, (uint2*)winh, n4);
        n4 = EDIM * EDIM / 4;
        conv_f16<<<(n4 + 255) / 256, 256>>>((const float4*)W_out, (uint2*)wouth, n4);
    }

    // 1) QKV projection -> fp32 qkv
    dim3 g1(3 * EDIM / 128, TOK / 128);
    gemm_hmma<<<g1, 256, GEMM_SMEM>>>(xh, winh, b_in, qkv, 3 * EDIM);

    // 2) Attention: one CTA per s, warp per head
    attn_kernel<<<SDIM, 256, ATT_SMEM>>>(qkv, oh);

    // 3) Output projection
    dim3 g3(EDIM / 128, TOK / 128);
    gemm_hmma<<<g3, 256, GEMM_SMEM>>>(oh, wouth, b_out, out, EDIM);
}